// round 8
// baseline (speedup 1.0000x reference)
#include <cuda_runtime.h>
#include <cuda_fp16.h>
#include <math.h>

#define BB   64
#define VV   2048
#define ENCD 128
#define TT   100
#define EMBD 256
#define DECD 512
#define ATTD 256
#define NVOC 29
#define XD   384   // EMB + ENC
#define NCH  16    // V-chunks of 128
#define NG   2048  // 4*DEC gate rows
#define KZ   896   // XD + DECD
#define NKC  7     // k-chunks of 128

#define PRED_OFF  0
#define ALPHA_OFF (BB*TT*NVOC)            // 185600
#define LEN_OFF   (ALPHA_OFF + BB*TT*VV)  // 13292800

// ---------------- scratch (device globals; no allocation allowed) ----------
__device__ __half g_enc_att_h[BB*VV*ATTD];  // 64 MB fp16
__device__ __half g_enc_h[BB*VV*ENCD];      // 32 MB fp16
__device__ __half g_wz[NG*KZ];              // 3.7 MB merged fp16 [W_ih | W_hh]
__device__ float  g_bz[NG];                 // merged bias
__device__ float  g_gpart[NKC*BB*NG];       // gate partials [kc][b][row]
__device__ float  g_h[BB*DECD];             // single h buffer (masked rows untouched)
__device__ float  g_c[BB*DECD];
__device__ float  g_dec_att[BB*ATTD];
__device__ float  g_gate[BB*ENCD];
__device__ float  g_part[BB*NCH*ENCD];      // partial awe [b][chunk][d]
__device__ float  g_psum[BB*NCH];           // partial expsum

__device__ __forceinline__ float sigf(float x) { return 1.f/(1.f+__expf(-x)); }

// ============================================================================
// Setup A: mean_enc -> h0,c0 ; heads(h0) for step 0 ; lengths to out tail
// grid(64), block(512)
// ============================================================================
__global__ void s_init(const float* __restrict__ enc, const int* __restrict__ lens,
                       const float* __restrict__ Wih_, const float* __restrict__ bih_,
                       const float* __restrict__ Wic_, const float* __restrict__ bic_,
                       const float* __restrict__ Wdec, const float* __restrict__ bdec,
                       const float* __restrict__ Wbeta, const float* __restrict__ bbeta,
                       float* __restrict__ out)
{
    int b = blockIdx.x, tid = threadIdx.x;
    __shared__ float red[16*128];
    __shared__ float mean[128];
    __shared__ float hs[512];
    int vr = tid >> 5, l = tid & 31;

    float4 acc = make_float4(0.f,0.f,0.f,0.f);
    for (int v = vr; v < VV; v += 16) {
        float4 e = *(const float4*)&enc[((size_t)(b*VV + v))*ENCD + l*4];
        acc.x += e.x; acc.y += e.y; acc.z += e.z; acc.w += e.w;
    }
    *(float4*)&red[vr*128 + l*4] = acc;
    __syncthreads();
    if (tid < 128) {
        float s = 0.f;
        #pragma unroll
        for (int i = 0; i < 16; i++) s += red[i*128 + tid];
        mean[tid] = s * (1.f/(float)VV);
    }
    __syncthreads();
    float ha = bih_[tid], ca = bic_[tid];
    const float* wh = Wih_ + (size_t)tid*ENCD;
    const float* wc = Wic_ + (size_t)tid*ENCD;
    #pragma unroll 4
    for (int k = 0; k < ENCD; k++) {
        float mk = mean[k];
        ha += mk * wh[k];
        ca += mk * wc[k];
    }
    g_h[b*DECD + tid] = ha;
    g_c[b*DECD + tid] = ca;
    hs[tid] = ha;
    if (tid == 0) out[LEN_OFF + b] = (float)lens[b];
    __syncthreads();

    // heads(h0): rows 0..383 (dec_att, gate) -- no pred from h0
    int sub = tid & 3, g = tid >> 2;
    #pragma unroll
    for (int pass = 0; pass < 3; pass++) {
        int row = pass*128 + g;
        const float* wrow; float bias; int kind;
        if (row < 256) { wrow = Wdec  + (size_t)row*DECD;       bias = bdec[row];       kind = 0; }
        else           { wrow = Wbeta + (size_t)(row-256)*DECD; bias = bbeta[row-256];  kind = 1; }
        float a = 0.f;
        #pragma unroll 8
        for (int i = 0; i < 32; i++) {
            int k = sub*4 + i*16;
            float4 w  = *(const float4*)&wrow[k];
            float4 hz = *(const float4*)&hs[k];
            a += w.x*hz.x + w.y*hz.y + w.z*hz.z + w.w*hz.w;
        }
        a += __shfl_xor_sync(0xffffffffu, a, 1);
        a += __shfl_xor_sync(0xffffffffu, a, 2);
        if (sub == 0) {
            a += bias;
            if (kind == 0) g_dec_att[b*ATTD + row] = a;
            else           g_gate[b*ENCD + (row-256)] = sigf(a);
        }
    }
}

// ============================================================================
// Setup W: merge LSTM weights to fp16 [row][XD | DECD], merged bias
// ============================================================================
__global__ void s_wlstm(const float* __restrict__ Wih, const float* __restrict__ bih,
                        const float* __restrict__ Whh, const float* __restrict__ bhh)
{
    int row = blockIdx.x, tid = threadIdx.x;
    for (int k = tid; k < XD; k += 256)
        g_wz[(size_t)row*KZ + k] = __float2half_rn(Wih[(size_t)row*XD + k]);
    for (int k = tid; k < DECD; k += 256)
        g_wz[(size_t)row*KZ + XD + k] = __float2half_rn(Whh[(size_t)row*DECD + k]);
    if (tid == 0) g_bz[row] = bih[row] + bhh[row];
}

// ============================================================================
// Setup B: enc_att(fp16) = enc @ W_enc.T + b_enc ; fp16 enc copy
// ============================================================================
#define EA_SMEM ((128*264 + 128*68)*4)
__global__ void __launch_bounds__(256)
s_encatt(const float* __restrict__ enc, const float* __restrict__ Wenc,
         const float* __restrict__ benc)
{
    extern __shared__ float sm[];
    float* Wt = sm;             // [128][264]
    float* Et = sm + 128*264;   // [128][68]
    int tid = threadIdx.x;
    int rowbase = blockIdx.x * 32;

    for (int i = tid; i < 256*128; i += 256) {
        int k = i & 127, a = i >> 7;
        Wt[k*264 + a] = Wenc[a*128 + k];
    }
    for (int i = tid; i < 32*128; i += 256) {
        int k = i & 127, r = i >> 7;
        Et[k*68 + r] = enc[(size_t)(rowbase + r)*128 + k];
    }
    __syncthreads();

    for (int i = tid; i < 32*128; i += 256) {
        int r = i >> 7, k = i & 127;
        g_enc_h[(size_t)(rowbase + r)*ENCD + k] = __float2half_rn(Et[k*68 + r]);
    }

    int tr = tid >> 5, ta = tid & 31;
    int r0 = tr*4, a0 = ta*8;
    float acc[4][8];
    #pragma unroll
    for (int i = 0; i < 4; i++)
        #pragma unroll
        for (int j = 0; j < 8; j++) acc[i][j] = 0.f;

    #pragma unroll 4
    for (int k = 0; k < 128; k++) {
        float4 rf = *(const float4*)&Et[k*68 + r0];
        float4 a4 = *(const float4*)&Wt[k*264 + a0];
        float4 b4 = *(const float4*)&Wt[k*264 + a0 + 4];
        float rr[4] = {rf.x, rf.y, rf.z, rf.w};
        float aa[8] = {a4.x,a4.y,a4.z,a4.w,b4.x,b4.y,b4.z,b4.w};
        #pragma unroll
        for (int i = 0; i < 4; i++)
            #pragma unroll
            for (int j = 0; j < 8; j++) acc[i][j] += rr[i]*aa[j];
    }
    float4 be0 = *(const float4*)&benc[a0];
    float4 be1 = *(const float4*)&benc[a0+4];
    float bb[8] = {be0.x,be0.y,be0.z,be0.w,be1.x,be1.y,be1.z,be1.w};
    #pragma unroll
    for (int i = 0; i < 4; i++) {
        size_t base = (size_t)(rowbase + r0 + i)*ATTD + a0;
        __half2 h[4];
        #pragma unroll
        for (int j = 0; j < 4; j++)
            h[j] = __floats2half2_rn(acc[i][2*j] + bb[2*j], acc[i][2*j+1] + bb[2*j+1]);
        *(uint4*)&g_enc_att_h[base] = *(uint4*)h;
    }
}

// ============================================================================
// kB: attention streamer.  grid(16,64), block 256 = 8 warps, NO barriers.
// scores -> exp -> unnormalized alphas to out, partial awe + expsum to globals.
// ============================================================================
__global__ void __launch_bounds__(256)
kB_atten(int t, const float* __restrict__ wfull, const int* __restrict__ lens,
         float* __restrict__ out)
{
    int b = blockIdx.y;
    if (t >= lens[b]) return;
    int tid = threadIdx.x;
    int warp = tid >> 5, l = tid & 31;
    int chunk = blockIdx.x;
    int vbase = chunk*128;

    __shared__ float al[128];
    __shared__ float wred[8];
    __shared__ float red[8*128];

    int a0 = l*8;
    __half2 d2[4]; float w[8];
    {
        float4 dd0 = *(const float4*)&g_dec_att[b*ATTD + a0];
        float4 dd1 = *(const float4*)&g_dec_att[b*ATTD + a0 + 4];
        d2[0] = __floats2half2_rn(dd0.x, dd0.y);
        d2[1] = __floats2half2_rn(dd0.z, dd0.w);
        d2[2] = __floats2half2_rn(dd1.x, dd1.y);
        d2[3] = __floats2half2_rn(dd1.z, dd1.w);
        float4 ww0 = *(const float4*)&wfull[a0];
        float4 ww1 = *(const float4*)&wfull[a0 + 4];
        w[0]=ww0.x; w[1]=ww0.y; w[2]=ww0.z; w[3]=ww0.w;
        w[4]=ww1.x; w[5]=ww1.y; w[6]=ww1.z; w[7]=ww1.w;
    }
    const __half2 z2 = __float2half2_rn(0.f);
    const __half* ea = g_enc_att_h + ((size_t)(b*VV + vbase))*ATTD;

    #pragma unroll
    for (int i = 0; i < 16; i += 4) {
        uint4 q[4];
        #pragma unroll
        for (int u = 0; u < 4; u++)
            q[u] = *(const uint4*)&ea[(size_t)((i+u)*8 + warp)*ATTD + a0];
        float s[4];
        #pragma unroll
        for (int u = 0; u < 4; u++) {
            const __half2* hh = (const __half2*)&q[u];
            float acc = 0.f;
            #pragma unroll
            for (int j = 0; j < 4; j++) {
                __half2 v = __hmax2(__hadd2(hh[j], d2[j]), z2);
                float2 f = __half22float2(v);
                acc += f.x*w[2*j] + f.y*w[2*j+1];
            }
            s[u] = acc;
        }
        #pragma unroll
        for (int o = 16; o; o >>= 1) {
            #pragma unroll
            for (int u = 0; u < 4; u++)
                s[u] += __shfl_xor_sync(0xffffffffu, s[u], o);
        }
        if (l == 0) {
            #pragma unroll
            for (int u = 0; u < 4; u++) al[(i+u)*8 + warp] = __expf(s[u]);
        }
    }
    __syncthreads();

    // unnormalized alphas + chunk expsum
    float e = (tid < 128) ? al[tid] : 0.f;
    if (tid < 128) out[ALPHA_OFF + ((size_t)b*TT + t)*VV + vbase + tid] = e;
    #pragma unroll
    for (int o = 16; o; o >>= 1) e += __shfl_xor_sync(0xffffffffu, e, o);
    if (l == 0) wred[warp] = e;

    // partial awe over the chunk's 128 rows
    const __half* eh = g_enc_h + ((size_t)(b*VV + vbase))*ENCD;
    float4 acc = make_float4(0.f,0.f,0.f,0.f);
    #pragma unroll 4
    for (int i = 0; i < 16; i++) {
        int r = i*8 + warp;
        float a = al[r];
        uint2 q = *(const uint2*)&eh[(size_t)r*ENCD + l*4];
        float2 e0 = __half22float2(((const __half2*)&q)[0]);
        float2 e1 = __half22float2(((const __half2*)&q)[1]);
        acc.x += a*e0.x; acc.y += a*e0.y; acc.z += a*e1.x; acc.w += a*e1.y;
    }
    *(float4*)&red[warp*128 + l*4] = acc;
    __syncthreads();
    if (tid < 128) {
        float s = 0.f;
        #pragma unroll
        for (int i = 0; i < 8; i++) s += red[i*128 + tid];
        g_part[(b*NCH + chunk)*ENCD + tid] = s;
    }
    if (tid == 0) {
        float ss = 0.f;
        #pragma unroll
        for (int i = 0; i < 8; i++) ss += wred[i];
        g_psum[b*NCH + chunk] = ss;
    }
}

// ============================================================================
// k6a: split-K LSTM GEMM with in-place x materialization in the z tile.
// grid(7, 32): kc x 64-row chunk, block 256.
// kc 0,1: z = emb ; kc 2: z = awe (combine partials) ; kc 3..6: z = h.
// ============================================================================
__global__ void __launch_bounds__(256)
k6a_gemm(int t, const int* __restrict__ lens,
         const int* __restrict__ captions, const float* __restrict__ embW)
{
    int kc = blockIdx.x, rc = blockIdx.y, tid = threadIdx.x;
    __shared__ float wt[128*68];   // [k][r]
    __shared__ float zt[128*68];   // [k][b]
    __shared__ float invs[64];
    __shared__ int   caps[64];

    int pred = (tid < 64) && (t < lens[tid]);
    int nb = __syncthreads_count(pred);   // active batch prefix (lens sorted desc)

    int kbase = kc * 128;
    int rowbase = rc * 64;

    if (kc == 2 && tid < 64) {
        float s = 0.f;
        #pragma unroll
        for (int r = 0; r < NCH; r++) s += g_psum[tid*NCH + r];
        invs[tid] = 1.f/s;
    }
    if (kc < 2 && tid < 64) caps[tid] = captions[tid*TT + t];
    __syncthreads();

    // weight tile: 64 rows x 128 halves
    for (int i = tid; i < 64*64; i += 256) {
        int r = i >> 6, kp = i & 63;
        unsigned int u = *(const unsigned int*)&g_wz[(size_t)(rowbase + r)*KZ + kbase + kp*2];
        float2 f = __half22float2(*(const __half2*)&u);
        wt[(kp*2  )*68 + r] = f.x;
        wt[(kp*2+1)*68 + r] = f.y;
    }
    // z tile [k][b]
    if (kc < 2) {
        for (int i = tid; i < 64*128; i += 256) {
            int b = i >> 7, k = i & 127;
            zt[k*68 + b] = embW[(size_t)caps[b]*EMBD + kbase + k];
        }
    } else if (kc == 2) {
        for (int i = tid; i < 64*128; i += 256) {
            int b = i >> 7, d = i & 127;
            float s = 0.f;
            #pragma unroll
            for (int r = 0; r < NCH; r++) s += g_part[(b*NCH + r)*ENCD + d];
            zt[d*68 + b] = s * invs[b] * g_gate[b*ENCD + d];
        }
    } else {
        for (int i = tid; i < 64*128; i += 256) {
            int b = i >> 7, k = i & 127;
            zt[k*68 + b] = g_h[b*DECD + (kbase - XD) + k];
        }
    }
    __syncthreads();

    int r0 = (tid & 15) * 4;
    int b0 = (tid >> 4) * 4;
    if (b0 >= nb) return;

    float acc[4][4];
    #pragma unroll
    for (int i = 0; i < 4; i++)
        #pragma unroll
        for (int j = 0; j < 4; j++) acc[i][j] = 0.f;

    #pragma unroll 4
    for (int k = 0; k < 128; k++) {
        float4 w = *(const float4*)&wt[k*68 + r0];
        float4 z = *(const float4*)&zt[k*68 + b0];
        float ww[4] = {w.x, w.y, w.z, w.w};
        float zz[4] = {z.x, z.y, z.z, z.w};
        #pragma unroll
        for (int i = 0; i < 4; i++)
            #pragma unroll
            for (int j = 0; j < 4; j++) acc[i][j] += ww[i]*zz[j];
    }
    #pragma unroll
    for (int j = 0; j < 4; j++) {
        *(float4*)&g_gpart[((size_t)(kc*BB + b0 + j))*NG + rowbase + r0] =
            make_float4(acc[0][j], acc[1][j], acc[2][j], acc[3][j]);
    }
}

// ============================================================================
// k6b: combine gate partials -> c,h update ; normalize alphas ;
//      heads(h_new): dec_att/gate for t+1, pred_t.   grid(64), block(512).
// ============================================================================
__global__ void __launch_bounds__(512)
k6b_cell(int t, const int* __restrict__ lens,
         const float* __restrict__ Wdec, const float* __restrict__ bdec,
         const float* __restrict__ Wbeta, const float* __restrict__ bbeta,
         const float* __restrict__ Wfin, const float* __restrict__ bfin,
         float* __restrict__ out)
{
    int b = blockIdx.x;
    if (t >= lens[b]) return;
    int tid = threadIdx.x;
    __shared__ float hn[512];
    __shared__ float ps[NCH];

    if (tid < NCH) ps[tid] = g_psum[b*NCH + tid];

    // gates: thread tid -> hidden unit j
    float g4[4];
    #pragma unroll
    for (int g = 0; g < 4; g++) {
        int row = g*DECD + tid;
        float s = g_bz[row];
        #pragma unroll
        for (int kc = 0; kc < NKC; kc++)
            s += g_gpart[((size_t)(kc*BB + b))*NG + row];
        g4[g] = s;
    }
    int hidx = b*DECD + tid;
    float si = sigf(g4[0]), sf = sigf(g4[1]), tg = tanhf(g4[2]), so = sigf(g4[3]);
    float cn = sf * g_c[hidx] + si * tg;
    g_c[hidx] = cn;
    float hv = so * tanhf(cn);
    g_h[hidx] = hv;
    hn[tid] = hv;
    __syncthreads();

    // normalize alphas
    float S = 0.f;
    #pragma unroll
    for (int i = 0; i < NCH; i++) S += ps[i];
    float invS = 1.f/S;
    float* ap = out + ALPHA_OFF + ((size_t)b*TT + t)*VV;
    #pragma unroll
    for (int u = 0; u < 4; u++) ap[u*512 + tid] *= invS;

    // heads(h_new): 413 rows (dec_att 256, gate 128, pred 29)
    int sub = tid & 3, g = tid >> 2;
    #pragma unroll
    for (int pass = 0; pass < 4; pass++) {
        int row = pass*128 + g;
        int rowc = row < 413 ? row : 412;
        const float* wrow; float bias; int kind;
        if (rowc < 256)      { wrow = Wdec  + (size_t)rowc*DECD;       bias = bdec[rowc];       kind = 0; }
        else if (rowc < 384) { wrow = Wbeta + (size_t)(rowc-256)*DECD; bias = bbeta[rowc-256];  kind = 1; }
        else                 { wrow = Wfin  + (size_t)(rowc-384)*DECD; bias = bfin[rowc-384];   kind = 2; }
        float a = 0.f;
        #pragma unroll 8
        for (int i = 0; i < 32; i++) {
            int k = sub*4 + i*16;
            float4 w  = *(const float4*)&wrow[k];
            float4 hz = *(const float4*)&hn[k];
            a += w.x*hz.x + w.y*hz.y + w.z*hz.z + w.w*hz.w;
        }
        a += __shfl_xor_sync(0xffffffffu, a, 1);
        a += __shfl_xor_sync(0xffffffffu, a, 2);
        if (sub == 0 && row < 413) {
            a += bias;
            if (kind == 0)      g_dec_att[b*ATTD + row] = a;
            else if (kind == 1) g_gate[b*ENCD + (row-256)] = sigf(a);
            else                out[PRED_OFF + ((size_t)b*TT + t)*NVOC + (row-384)] = a;
        }
    }
}

// ============================================================================
extern "C" void kernel_launch(void* const* d_in, const int* in_sizes, int n_in,
                              void* d_out, int out_size)
{
    const float* enc      = (const float*)d_in[0];
    const int*   captions = (const int*)  d_in[1];
    const int*   lens     = (const int*)  d_in[2];
    const float* embW     = (const float*)d_in[3];
    const float* Wenc     = (const float*)d_in[4];
    const float* benc     = (const float*)d_in[5];
    const float* Wdec     = (const float*)d_in[6];
    const float* bdec     = (const float*)d_in[7];
    const float* wfull    = (const float*)d_in[8];
    // d_in[9] = b_full : dropped (softmax shift-invariant)
    const float* Wih      = (const float*)d_in[10];
    const float* bih      = (const float*)d_in[11];
    const float* Whh      = (const float*)d_in[12];
    const float* bhh      = (const float*)d_in[13];
    const float* Winith   = (const float*)d_in[14];
    const float* binith   = (const float*)d_in[15];
    const float* Winitc   = (const float*)d_in[16];
    const float* binitc   = (const float*)d_in[17];
    const float* Wbeta    = (const float*)d_in[18];
    const float* bbeta    = (const float*)d_in[19];
    const float* Wfin     = (const float*)d_in[20];
    const float* bfin     = (const float*)d_in[21];
    float* out = (float*)d_out;

    cudaFuncSetAttribute(s_encatt, cudaFuncAttributeMaxDynamicSharedMemorySize, EA_SMEM);

    cudaMemsetAsync(d_out, 0, (size_t)out_size*sizeof(float), 0);

    s_init<<<BB, 512>>>(enc, lens, Winith, binith, Winitc, binitc,
                        Wdec, bdec, Wbeta, bbeta, out);
    s_wlstm<<<NG, 256>>>(Wih, bih, Whh, bhh);
    s_encatt<<<(BB*VV)/32, 256, EA_SMEM>>>(enc, Wenc, benc);

    for (int t = 0; t < TT; t++) {
        kB_atten<<<dim3(NCH, BB), 256>>>(t, wfull, lens, out);
        k6a_gemm<<<dim3(NKC, 32), 256>>>(t, lens, captions, embW);
        k6b_cell<<<BB, 512>>>(t, lens, Wdec, bdec, Wbeta, bbeta, Wfin, bfin, out);
    }
}

// round 9
// speedup vs baseline: 1.2420x; 1.2420x over previous
#include <cuda_runtime.h>
#include <cuda_fp16.h>
#include <math.h>

#define BB   64
#define VV   2048
#define ENCD 128
#define TT   100
#define EMBD 256
#define DECD 512
#define ATTD 256
#define NVOC 29
#define XD   384   // EMB + ENC
#define NCH  16    // V-chunks of 128
#define NG   2048  // 4*DEC gate rows
#define KZ   896   // XD + DECD
#define NKC  7     // k-chunks of 128

#define PRED_OFF  0
#define ALPHA_OFF (BB*TT*NVOC)            // 185600
#define LEN_OFF   (ALPHA_OFF + BB*TT*VV)  // 13292800

// ---------------- scratch (device globals; no allocation allowed) ----------
__device__ __half g_enc_att_h[BB*VV*ATTD];  // 64 MB fp16
__device__ __half g_enc_h[BB*VV*ENCD];      // 32 MB fp16
__device__ __half g_wz[NG*KZ];              // 3.7 MB merged fp16 [W_ih | W_hh]
__device__ float  g_bz[NG];                 // merged bias
__device__ float  g_gpart[NKC*BB*NG];       // gate partials [kc][b][row]
__device__ float  g_h[BB*DECD];             // h buffer (read by k6a)
__device__ float  g_cbuf[2][BB*DECD];       // ping-pong c (race-free multi-block cell)
__device__ float  g_dec_att[BB*ATTD];
__device__ float  g_gate[BB*ENCD];
__device__ float  g_part[BB*NCH*ENCD];      // partial awe [b][chunk][d]
__device__ float  g_psum[BB*NCH];           // partial expsum

__device__ __forceinline__ float sigf(float x) { return 1.f/(1.f+__expf(-x)); }

// ============================================================================
// Setup A: mean_enc -> h0,c0 ; heads(h0) for step 0 ; lengths to out tail
// grid(64), block(512)
// ============================================================================
__global__ void s_init(const float* __restrict__ enc, const int* __restrict__ lens,
                       const float* __restrict__ Wih_, const float* __restrict__ bih_,
                       const float* __restrict__ Wic_, const float* __restrict__ bic_,
                       const float* __restrict__ Wdec, const float* __restrict__ bdec,
                       const float* __restrict__ Wbeta, const float* __restrict__ bbeta,
                       float* __restrict__ out)
{
    int b = blockIdx.x, tid = threadIdx.x;
    __shared__ float red[16*128];
    __shared__ float mean[128];
    __shared__ float hs[512];
    int vr = tid >> 5, l = tid & 31;

    float4 acc = make_float4(0.f,0.f,0.f,0.f);
    for (int v = vr; v < VV; v += 16) {
        float4 e = *(const float4*)&enc[((size_t)(b*VV + v))*ENCD + l*4];
        acc.x += e.x; acc.y += e.y; acc.z += e.z; acc.w += e.w;
    }
    *(float4*)&red[vr*128 + l*4] = acc;
    __syncthreads();
    if (tid < 128) {
        float s = 0.f;
        #pragma unroll
        for (int i = 0; i < 16; i++) s += red[i*128 + tid];
        mean[tid] = s * (1.f/(float)VV);
    }
    __syncthreads();
    float ha = bih_[tid], ca = bic_[tid];
    const float* wh = Wih_ + (size_t)tid*ENCD;
    const float* wc = Wic_ + (size_t)tid*ENCD;
    #pragma unroll 4
    for (int k = 0; k < ENCD; k++) {
        float mk = mean[k];
        ha += mk * wh[k];
        ca += mk * wc[k];
    }
    g_h[b*DECD + tid] = ha;
    g_cbuf[0][b*DECD + tid] = ca;
    hs[tid] = ha;
    if (tid == 0) out[LEN_OFF + b] = (float)lens[b];
    __syncthreads();

    // heads(h0): rows 0..383 (dec_att, gate) -- no pred from h0
    int sub = tid & 3, g = tid >> 2;
    #pragma unroll
    for (int pass = 0; pass < 3; pass++) {
        int row = pass*128 + g;
        const float* wrow; float bias; int kind;
        if (row < 256) { wrow = Wdec  + (size_t)row*DECD;       bias = bdec[row];       kind = 0; }
        else           { wrow = Wbeta + (size_t)(row-256)*DECD; bias = bbeta[row-256];  kind = 1; }
        float a = 0.f;
        #pragma unroll 8
        for (int i = 0; i < 32; i++) {
            int k = sub*4 + i*16;
            float4 w  = *(const float4*)&wrow[k];
            float4 hz = *(const float4*)&hs[k];
            a += w.x*hz.x + w.y*hz.y + w.z*hz.z + w.w*hz.w;
        }
        a += __shfl_xor_sync(0xffffffffu, a, 1);
        a += __shfl_xor_sync(0xffffffffu, a, 2);
        if (sub == 0) {
            a += bias;
            if (kind == 0) g_dec_att[b*ATTD + row] = a;
            else           g_gate[b*ENCD + (row-256)] = sigf(a);
        }
    }
}

// ============================================================================
// Setup W: merge LSTM weights to fp16 [row][XD | DECD], merged bias
// ============================================================================
__global__ void s_wlstm(const float* __restrict__ Wih, const float* __restrict__ bih,
                        const float* __restrict__ Whh, const float* __restrict__ bhh)
{
    int row = blockIdx.x, tid = threadIdx.x;
    for (int k = tid; k < XD; k += 256)
        g_wz[(size_t)row*KZ + k] = __float2half_rn(Wih[(size_t)row*XD + k]);
    for (int k = tid; k < DECD; k += 256)
        g_wz[(size_t)row*KZ + XD + k] = __float2half_rn(Whh[(size_t)row*DECD + k]);
    if (tid == 0) g_bz[row] = bih[row] + bhh[row];
}

// ============================================================================
// Setup B: enc_att(fp16) = enc @ W_enc.T + b_enc ; fp16 enc copy
// ============================================================================
#define EA_SMEM ((128*264 + 128*68)*4)
__global__ void __launch_bounds__(256)
s_encatt(const float* __restrict__ enc, const float* __restrict__ Wenc,
         const float* __restrict__ benc)
{
    extern __shared__ float sm[];
    float* Wt = sm;             // [128][264]
    float* Et = sm + 128*264;   // [128][68]
    int tid = threadIdx.x;
    int rowbase = blockIdx.x * 32;

    for (int i = tid; i < 256*128; i += 256) {
        int k = i & 127, a = i >> 7;
        Wt[k*264 + a] = Wenc[a*128 + k];
    }
    for (int i = tid; i < 32*128; i += 256) {
        int k = i & 127, r = i >> 7;
        Et[k*68 + r] = enc[(size_t)(rowbase + r)*128 + k];
    }
    __syncthreads();

    for (int i = tid; i < 32*128; i += 256) {
        int r = i >> 7, k = i & 127;
        g_enc_h[(size_t)(rowbase + r)*ENCD + k] = __float2half_rn(Et[k*68 + r]);
    }

    int tr = tid >> 5, ta = tid & 31;
    int r0 = tr*4, a0 = ta*8;
    float acc[4][8];
    #pragma unroll
    for (int i = 0; i < 4; i++)
        #pragma unroll
        for (int j = 0; j < 8; j++) acc[i][j] = 0.f;

    #pragma unroll 4
    for (int k = 0; k < 128; k++) {
        float4 rf = *(const float4*)&Et[k*68 + r0];
        float4 a4 = *(const float4*)&Wt[k*264 + a0];
        float4 b4 = *(const float4*)&Wt[k*264 + a0 + 4];
        float rr[4] = {rf.x, rf.y, rf.z, rf.w};
        float aa[8] = {a4.x,a4.y,a4.z,a4.w,b4.x,b4.y,b4.z,b4.w};
        #pragma unroll
        for (int i = 0; i < 4; i++)
            #pragma unroll
            for (int j = 0; j < 8; j++) acc[i][j] += rr[i]*aa[j];
    }
    float4 be0 = *(const float4*)&benc[a0];
    float4 be1 = *(const float4*)&benc[a0+4];
    float bb[8] = {be0.x,be0.y,be0.z,be0.w,be1.x,be1.y,be1.z,be1.w};
    #pragma unroll
    for (int i = 0; i < 4; i++) {
        size_t base = (size_t)(rowbase + r0 + i)*ATTD + a0;
        __half2 h[4];
        #pragma unroll
        for (int j = 0; j < 4; j++)
            h[j] = __floats2half2_rn(acc[i][2*j] + bb[2*j], acc[i][2*j+1] + bb[2*j+1]);
        *(uint4*)&g_enc_att_h[base] = *(uint4*)h;
    }
}

// ============================================================================
// kB: attention streamer.  grid(16,64), block 256 = 8 warps, NO barriers.
// scores -> exp -> unnormalized alphas to out, partial awe + expsum to globals.
// ============================================================================
__global__ void __launch_bounds__(256)
kB_atten(int t, const float* __restrict__ wfull, const int* __restrict__ lens,
         float* __restrict__ out)
{
    int b = blockIdx.y;
    if (t >= lens[b]) return;
    int tid = threadIdx.x;
    int warp = tid >> 5, l = tid & 31;
    int chunk = blockIdx.x;
    int vbase = chunk*128;

    __shared__ float al[128];
    __shared__ float wred[8];
    __shared__ float red[8*128];

    int a0 = l*8;
    __half2 d2[4]; float w[8];
    {
        float4 dd0 = *(const float4*)&g_dec_att[b*ATTD + a0];
        float4 dd1 = *(const float4*)&g_dec_att[b*ATTD + a0 + 4];
        d2[0] = __floats2half2_rn(dd0.x, dd0.y);
        d2[1] = __floats2half2_rn(dd0.z, dd0.w);
        d2[2] = __floats2half2_rn(dd1.x, dd1.y);
        d2[3] = __floats2half2_rn(dd1.z, dd1.w);
        float4 ww0 = *(const float4*)&wfull[a0];
        float4 ww1 = *(const float4*)&wfull[a0 + 4];
        w[0]=ww0.x; w[1]=ww0.y; w[2]=ww0.z; w[3]=ww0.w;
        w[4]=ww1.x; w[5]=ww1.y; w[6]=ww1.z; w[7]=ww1.w;
    }
    const __half2 z2 = __float2half2_rn(0.f);
    const __half* ea = g_enc_att_h + ((size_t)(b*VV + vbase))*ATTD;

    #pragma unroll
    for (int i = 0; i < 16; i += 4) {
        uint4 q[4];
        #pragma unroll
        for (int u = 0; u < 4; u++)
            q[u] = *(const uint4*)&ea[(size_t)((i+u)*8 + warp)*ATTD + a0];
        float s[4];
        #pragma unroll
        for (int u = 0; u < 4; u++) {
            const __half2* hh = (const __half2*)&q[u];
            float acc = 0.f;
            #pragma unroll
            for (int j = 0; j < 4; j++) {
                __half2 v = __hmax2(__hadd2(hh[j], d2[j]), z2);
                float2 f = __half22float2(v);
                acc += f.x*w[2*j] + f.y*w[2*j+1];
            }
            s[u] = acc;
        }
        #pragma unroll
        for (int o = 16; o; o >>= 1) {
            #pragma unroll
            for (int u = 0; u < 4; u++)
                s[u] += __shfl_xor_sync(0xffffffffu, s[u], o);
        }
        if (l == 0) {
            #pragma unroll
            for (int u = 0; u < 4; u++) al[(i+u)*8 + warp] = __expf(s[u]);
        }
    }
    __syncthreads();

    // unnormalized alphas + chunk expsum
    float e = (tid < 128) ? al[tid] : 0.f;
    if (tid < 128) out[ALPHA_OFF + ((size_t)b*TT + t)*VV + vbase + tid] = e;
    #pragma unroll
    for (int o = 16; o; o >>= 1) e += __shfl_xor_sync(0xffffffffu, e, o);
    if (l == 0) wred[warp] = e;

    // partial awe over the chunk's 128 rows
    const __half* eh = g_enc_h + ((size_t)(b*VV + vbase))*ENCD;
    float4 acc = make_float4(0.f,0.f,0.f,0.f);
    #pragma unroll 4
    for (int i = 0; i < 16; i++) {
        int r = i*8 + warp;
        float a = al[r];
        uint2 q = *(const uint2*)&eh[(size_t)r*ENCD + l*4];
        float2 e0 = __half22float2(((const __half2*)&q)[0]);
        float2 e1 = __half22float2(((const __half2*)&q)[1]);
        acc.x += a*e0.x; acc.y += a*e0.y; acc.z += a*e1.x; acc.w += a*e1.y;
    }
    *(float4*)&red[warp*128 + l*4] = acc;
    __syncthreads();
    if (tid < 128) {
        float s = 0.f;
        #pragma unroll
        for (int i = 0; i < 8; i++) s += red[i*128 + tid];
        g_part[(b*NCH + chunk)*ENCD + tid] = s;
    }
    if (tid == 0) {
        float ss = 0.f;
        #pragma unroll
        for (int i = 0; i < 8; i++) ss += wred[i];
        g_psum[b*NCH + chunk] = ss;
    }
}

// ============================================================================
// k6a: split-K LSTM GEMM with in-place x materialization in the z tile.
// grid(7, 32): kc x 64-row chunk, block 256.
// kc 0,1: z = emb ; kc 2: z = awe (combine partials) ; kc 3..6: z = h.
// ============================================================================
__global__ void __launch_bounds__(256)
k6a_gemm(int t, const int* __restrict__ lens,
         const int* __restrict__ captions, const float* __restrict__ embW)
{
    int kc = blockIdx.x, rc = blockIdx.y, tid = threadIdx.x;
    __shared__ float wt[128*68];   // [k][r]
    __shared__ float zt[128*68];   // [k][b]
    __shared__ float invs[64];
    __shared__ int   caps[64];

    int pred = (tid < 64) && (t < lens[tid]);
    int nb = __syncthreads_count(pred);   // active batch prefix (lens sorted desc)

    int kbase = kc * 128;
    int rowbase = rc * 64;

    if (kc == 2 && tid < 64) {
        float s = 0.f;
        #pragma unroll
        for (int r = 0; r < NCH; r++) s += g_psum[tid*NCH + r];
        invs[tid] = 1.f/s;
    }
    if (kc < 2 && tid < 64) caps[tid] = captions[tid*TT + t];
    __syncthreads();

    // weight tile: 64 rows x 128 halves
    for (int i = tid; i < 64*64; i += 256) {
        int r = i >> 6, kp = i & 63;
        unsigned int u = *(const unsigned int*)&g_wz[(size_t)(rowbase + r)*KZ + kbase + kp*2];
        float2 f = __half22float2(*(const __half2*)&u);
        wt[(kp*2  )*68 + r] = f.x;
        wt[(kp*2+1)*68 + r] = f.y;
    }
    // z tile [k][b]
    if (kc < 2) {
        for (int i = tid; i < 64*128; i += 256) {
            int b = i >> 7, k = i & 127;
            zt[k*68 + b] = embW[(size_t)caps[b]*EMBD + kbase + k];
        }
    } else if (kc == 2) {
        for (int i = tid; i < 64*128; i += 256) {
            int b = i >> 7, d = i & 127;
            float s = 0.f;
            #pragma unroll
            for (int r = 0; r < NCH; r++) s += g_part[(b*NCH + r)*ENCD + d];
            zt[d*68 + b] = s * invs[b] * g_gate[b*ENCD + d];
        }
    } else {
        for (int i = tid; i < 64*128; i += 256) {
            int b = i >> 7, k = i & 127;
            zt[k*68 + b] = g_h[b*DECD + (kbase - XD) + k];
        }
    }
    __syncthreads();

    int r0 = (tid & 15) * 4;
    int b0 = (tid >> 4) * 4;
    if (b0 >= nb) return;

    float acc[4][4];
    #pragma unroll
    for (int i = 0; i < 4; i++)
        #pragma unroll
        for (int j = 0; j < 4; j++) acc[i][j] = 0.f;

    #pragma unroll 4
    for (int k = 0; k < 128; k++) {
        float4 w = *(const float4*)&wt[k*68 + r0];
        float4 z = *(const float4*)&zt[k*68 + b0];
        float ww[4] = {w.x, w.y, w.z, w.w};
        float zz[4] = {z.x, z.y, z.z, z.w};
        #pragma unroll
        for (int i = 0; i < 4; i++)
            #pragma unroll
            for (int j = 0; j < 4; j++) acc[i][j] += ww[i]*zz[j];
    }
    #pragma unroll
    for (int j = 0; j < 4; j++) {
        *(float4*)&g_gpart[((size_t)(kc*BB + b0 + j))*NG + rowbase + r0] =
            make_float4(acc[0][j], acc[1][j], acc[2][j], acc[3][j]);
    }
}

// ============================================================================
// k6b: cell + heads, parallel.  grid(64, 4), block(512).
// Every block of a b redundantly recombines gates -> h_new (smem).
// by==0 writes c (ping-pong) and h.  Each by: quarter of alphas-normalize +
// quarter of 413 head rows (dec_att/gate for t+1, pred_t).
// ============================================================================
__global__ void __launch_bounds__(512)
k6b_cell(int t, const int* __restrict__ lens,
         const float* __restrict__ Wdec, const float* __restrict__ bdec,
         const float* __restrict__ Wbeta, const float* __restrict__ bbeta,
         const float* __restrict__ Wfin, const float* __restrict__ bfin,
         float* __restrict__ out)
{
    int b = blockIdx.x;
    if (t >= lens[b]) return;
    int by = blockIdx.y;
    int tid = threadIdx.x;
    __shared__ float hn[512];
    __shared__ float ps[NCH];

    if (tid < NCH) ps[tid] = g_psum[b*NCH + tid];

    // gates: thread tid -> hidden unit j (redundant across by)
    float g4[4];
    #pragma unroll
    for (int g = 0; g < 4; g++) {
        int row = g*DECD + tid;
        float s = g_bz[row];
        #pragma unroll
        for (int kc = 0; kc < NKC; kc++)
            s += g_gpart[((size_t)(kc*BB + b))*NG + row];
        g4[g] = s;
    }
    int hidx = b*DECD + tid;
    int p = t & 1;
    float si = sigf(g4[0]), sf = sigf(g4[1]), tg = tanhf(g4[2]), so = sigf(g4[3]);
    float cn = sf * g_cbuf[p][hidx] + si * tg;
    float hv = so * tanhf(cn);
    if (by == 0) { g_cbuf[1-p][hidx] = cn; g_h[hidx] = hv; }
    hn[tid] = hv;
    __syncthreads();

    // normalize this block's quarter of the alphas
    float S = 0.f;
    #pragma unroll
    for (int i = 0; i < NCH; i++) S += ps[i];
    float invS = 1.f/S;
    out[ALPHA_OFF + ((size_t)b*TT + t)*VV + by*512 + tid] *= invS;

    // heads(h_new): quarter of 413 rows
    int sub = tid & 3, g = tid >> 2;   // g: 0..127
    int row = by*104 + g;
    if (g < 104 && row < 413) {
        const float* wrow; float bias; int kind;
        if (row < 256)      { wrow = Wdec  + (size_t)row*DECD;       bias = bdec[row];       kind = 0; }
        else if (row < 384) { wrow = Wbeta + (size_t)(row-256)*DECD; bias = bbeta[row-256];  kind = 1; }
        else                { wrow = Wfin  + (size_t)(row-384)*DECD; bias = bfin[row-384];   kind = 2; }
        float a = 0.f;
        #pragma unroll 8
        for (int i = 0; i < 32; i++) {
            int k = sub*4 + i*16;
            float4 w  = *(const float4*)&wrow[k];
            float4 hz = *(const float4*)&hn[k];
            a += w.x*hz.x + w.y*hz.y + w.z*hz.z + w.w*hz.w;
        }
        a += __shfl_xor_sync(0xffffffffu, a, 1);
        a += __shfl_xor_sync(0xffffffffu, a, 2);
        if (sub == 0) {
            a += bias;
            if (kind == 0)      g_dec_att[b*ATTD + row] = a;
            else if (kind == 1) g_gate[b*ENCD + (row-256)] = sigf(a);
            else                out[PRED_OFF + ((size_t)b*TT + t)*NVOC + (row-384)] = a;
        }
    }
}

// ============================================================================
extern "C" void kernel_launch(void* const* d_in, const int* in_sizes, int n_in,
                              void* d_out, int out_size)
{
    const float* enc      = (const float*)d_in[0];
    const int*   captions = (const int*)  d_in[1];
    const int*   lens     = (const int*)  d_in[2];
    const float* embW     = (const float*)d_in[3];
    const float* Wenc     = (const float*)d_in[4];
    const float* benc     = (const float*)d_in[5];
    const float* Wdec     = (const float*)d_in[6];
    const float* bdec     = (const float*)d_in[7];
    const float* wfull    = (const float*)d_in[8];
    // d_in[9] = b_full : dropped (softmax shift-invariant)
    const float* Wih      = (const float*)d_in[10];
    const float* bih      = (const float*)d_in[11];
    const float* Whh      = (const float*)d_in[12];
    const float* bhh      = (const float*)d_in[13];
    const float* Winith   = (const float*)d_in[14];
    const float* binith   = (const float*)d_in[15];
    const float* Winitc   = (const float*)d_in[16];
    const float* binitc   = (const float*)d_in[17];
    const float* Wbeta    = (const float*)d_in[18];
    const float* bbeta    = (const float*)d_in[19];
    const float* Wfin     = (const float*)d_in[20];
    const float* bfin     = (const float*)d_in[21];
    float* out = (float*)d_out;

    cudaFuncSetAttribute(s_encatt, cudaFuncAttributeMaxDynamicSharedMemorySize, EA_SMEM);

    cudaMemsetAsync(d_out, 0, (size_t)out_size*sizeof(float), 0);

    s_init<<<BB, 512>>>(enc, lens, Winith, binith, Winitc, binitc,
                        Wdec, bdec, Wbeta, bbeta, out);
    s_wlstm<<<NG, 256>>>(Wih, bih, Whh, bhh);
    s_encatt<<<(BB*VV)/32, 256, EA_SMEM>>>(enc, Wenc, benc);

    for (int t = 0; t < TT; t++) {
        kB_atten<<<dim3(NCH, BB), 256>>>(t, wfull, lens, out);
        k6a_gemm<<<dim3(NKC, 32), 256>>>(t, lens, captions, embW);
        k6b_cell<<<dim3(BB, 4), 512>>>(t, lens, Wdec, bdec, Wbeta, bbeta,
                                       Wfin, bfin, out);
    }
}